// round 6
// baseline (speedup 1.0000x reference)
#include <cuda_runtime.h>
#include <cstdint>

#define BATCH   1024
#define SENS    128
#define NSTATE  256
#define MOUT    32
#define NUNFOLD 6
#define BB      8          // batch rows per block
#define HB      4          // batch rows per thread (two 256-thread halves)
#define EPSV    1e-8f
#define CAP_R   176        // max active pre-neurons per column
#define CAP_S   104        // sensory cap

// Compacted params (indexed by SLOT = sorted column order), tanh form:
//   sigmoid(s*(v-m)) = 0.5 + 0.5*tanh(0.5*s*(v-m))
//   x = 0.5*sigma (low 8 mantissa bits carry pre-neuron index)
//   y = -0.5*sigma*mu,  z = 0.5*w*mask,  w = 0.5*w*erev*mask
__device__ float4 g_cparams[CAP_R * NSTATE];
__device__ float4 g_csparams[CAP_S * NSTATE];
__device__ int    g_ccnt[NSTATE];
__device__ int    g_cscnt[NSTATE];
__device__ float2 g_col[NSTATE];
__device__ float2 g_scol[NSTATE];
__device__ int    g_rcntJ[NSTATE];
__device__ int    g_scntJ[NSTATE];
__device__ int    g_perm[NSTATE];     // slot -> column

__device__ __forceinline__ float ftanh(float x) {
    float y; asm("tanh.approx.f32 %0, %1;" : "=f"(y) : "f"(x)); return y;
}
__device__ __forceinline__ float frcp(float x) {
    float y; asm("rcp.approx.ftz.f32 %0, %1;" : "=f"(y) : "f"(x)); return y;
}

// ---- Pass 1: per-column active counts (one warp per column) ----
__global__ void count_kernel(const float* __restrict__ mask,
                             const float* __restrict__ smask)
{
    int warp = (blockIdx.x * blockDim.x + threadIdx.x) >> 5;
    int lane = threadIdx.x & 31;
    if (warp >= NSTATE) return;
    int j = warp;
    int rc = 0, sc = 0;
    for (int i = lane; i < NSTATE; i += 32) rc += (mask [i * NSTATE + j] != 0.0f);
    for (int s = lane; s < SENS;   s += 32) sc += (smask[s * NSTATE + j] != 0.0f);
    #pragma unroll
    for (int o = 16; o; o >>= 1) {
        rc += __shfl_xor_sync(0xFFFFFFFFu, rc, o);
        sc += __shfl_xor_sync(0xFFFFFFFFu, sc, o);
    }
    if (lane == 0) { g_rcntJ[j] = rc; g_scntJ[j] = sc; }
}

// ---- Pass 2: deterministic rank by weight, slot->column perm ----
__global__ void rank_kernel()
{
    __shared__ int key[NSTATE];
    int j = threadIdx.x;
    key[j] = NUNFOLD * g_rcntJ[j] + g_scntJ[j];
    __syncthreads();
    int kj = key[j];
    int r = 0;
    for (int k = 0; k < NSTATE; k++) {
        int kk = key[k];
        r += (kk < kj) || (kk == kj && k < j);
    }
    g_perm[r] = j;
}

// ---- Pass 3: order-preserving warp compaction into slot-major storage ----
__global__ void compact_kernel(const float* __restrict__ sigma, const float* __restrict__ mu,
                               const float* __restrict__ w,     const float* __restrict__ erev,
                               const float* __restrict__ mask,
                               const float* __restrict__ ssigma, const float* __restrict__ smu,
                               const float* __restrict__ sw,     const float* __restrict__ serev,
                               const float* __restrict__ smask)
{
    int warp = (blockIdx.x * blockDim.x + threadIdx.x) >> 5;
    int lane = threadIdx.x & 31;
    if (warp >= 2 * NSTATE) return;

    if (warp < NSTATE) {
        const int slot = warp;
        const int j    = g_perm[slot];
        int c = 0; float sz = 0.0f, sn = 0.0f;
        for (int base = 0; base < NSTATE; base += 32) {
            int i   = base + lane;
            int off = i * NSTATE + j;
            float m = mask[off];
            bool act = (m != 0.0f);
            unsigned bal = __ballot_sync(0xFFFFFFFFu, act);
            int pos = c + __popc(bal & ((1u << lane) - 1u));
            if (act) {
                float sg = 0.5f * sigma[off];
                float y  = -sg * mu[off];
                float z  = 0.5f * w[off] * m;
                float wn = 0.5f * w[off] * erev[off] * m;
                uint32_t xb = (__float_as_uint(sg) & 0xFFFFFF00u) | (uint32_t)i;
                sz += z; sn += wn;
                if (pos < CAP_R)
                    g_cparams[pos * NSTATE + slot] = make_float4(__uint_as_float(xb), y, z, wn);
            }
            c += __popc(bal);
        }
        #pragma unroll
        for (int o = 16; o; o >>= 1) {
            sz += __shfl_xor_sync(0xFFFFFFFFu, sz, o);
            sn += __shfl_xor_sync(0xFFFFFFFFu, sn, o);
        }
        int cnt = (c < CAP_R) ? c : CAP_R;
        if (lane == 0) { g_ccnt[slot] = cnt; g_col[slot] = make_float2(sz, sn); }
    } else {
        const int sslot = warp - NSTATE;
        const int j     = g_perm[sslot];
        int c = 0; float sz = 0.0f, sn = 0.0f;
        for (int base = 0; base < SENS; base += 32) {
            int s   = base + lane;
            int off = s * NSTATE + j;
            float m = smask[off];
            bool act = (m != 0.0f);
            unsigned bal = __ballot_sync(0xFFFFFFFFu, act);
            int pos = c + __popc(bal & ((1u << lane) - 1u));
            if (act) {
                float sg = 0.5f * ssigma[off];
                float y  = -sg * smu[off];
                float z  = 0.5f * sw[off] * m;
                float wn = 0.5f * sw[off] * serev[off] * m;
                uint32_t xb = (__float_as_uint(sg) & 0xFFFFFF00u) | (uint32_t)s;
                sz += z; sn += wn;
                if (pos < CAP_S)
                    g_csparams[pos * NSTATE + sslot] = make_float4(__uint_as_float(xb), y, z, wn);
            }
            c += __popc(bal);
        }
        #pragma unroll
        for (int o = 16; o; o >>= 1) {
            sz += __shfl_xor_sync(0xFFFFFFFFu, sz, o);
            sn += __shfl_xor_sync(0xFFFFFFFFu, sn, o);
        }
        int cnt = (c < CAP_S) ? c : CAP_S;
        if (lane == 0) { g_cscnt[sslot] = cnt; g_scol[sslot] = make_float2(sz, sn); }
    }
}

// ---- Pass 4: bank-group scheduling ----
// Reorder each slot's entry list so that at loop step k, slot t reads shared
// bank-group (t+k)&7  => any 8 consecutive lanes in an LDS.128 phase hit 8
// distinct 16B bank-groups => conflict-free gathers. Padding entries are
// group-aligned with z=w=0.
__global__ void reorder_kernel()
{
    const int slot = threadIdx.x;
    const bool rec = (blockIdx.x == 0);
    const int cnt  = rec ? g_ccnt[slot] : g_cscnt[slot];
    const int CAP  = rec ? CAP_R : CAP_S;
    float4* buf    = rec ? g_cparams : g_csparams;

    float4  ent[CAP_R];
    uint8_t bins[8][64];
    int bcnt[8]  = {0,0,0,0,0,0,0,0};
    int bhead[8] = {0,0,0,0,0,0,0,0};

    for (int c = 0; c < cnt; c++) {
        float4 e = buf[c * NSTATE + slot];
        ent[c] = e;
        int g = (int)(__float_as_uint(e.x) & 7u);
        while (bcnt[g] >= 64) g = (g + 1) & 7;   // overflow probe (rare)
        bins[g][bcnt[g]++] = (uint8_t)c;
    }
    for (int k = 0; k < cnt; k++) {
        int g = (slot + k) & 7;
        while (bhead[g] >= bcnt[g]) g = (g + 1) & 7;  // fallback (rare)
        buf[k * NSTATE + slot] = ent[bins[g][bhead[g]++]];
    }
    for (int k = cnt; k < CAP; k++) {
        uint32_t xb = __float_as_uint(1.0f) | (uint32_t)((slot + k) & 7);
        buf[k * NSTATE + slot] = make_float4(__uint_as_float(xb), 0.0f, 0.0f, 0.0f);
    }
}

// ---- Main kernel ----
__global__ __launch_bounds__(512, 1)
void ltc_kernel(const float* __restrict__ inputs, const float* __restrict__ states,
                const float* __restrict__ gleak,  const float* __restrict__ vleak,
                const float* __restrict__ cm,
                const float* __restrict__ input_w, const float* __restrict__ input_b,
                const float* __restrict__ output_w, const float* __restrict__ output_b,
                float* __restrict__ out)
{
    __shared__ float4 sx4[2][SENS];      // mapped sensory inputs
    __shared__ float4 sv4[2][NSTATE];    // current state

    const int tid = threadIdx.x;
    const int t   = tid & (NSTATE - 1);  // slot
    const int h   = tid >> 8;            // batch half
    const int b0  = blockIdx.x * BB;
    const int j   = g_perm[t];           // this thread's column

    float* sxf = (float*)sx4;
    float* svf = (float*)sv4;
    for (int q = tid; q < BB * SENS; q += 512) {
        int bb = q >> 7, s = q & (SENS - 1);
        sxf[((bb >> 2) * SENS + s) * 4 + (bb & 3)] =
            inputs[(b0 + bb) * SENS + s] * input_w[s] + input_b[s];
    }
    for (int q = tid; q < BB * NSTATE; q += 512) {
        int bb = q >> 8, jj = q & (NSTATE - 1);
        svf[((bb >> 2) * NSTATE + jj) * 4 + (bb & 3)] =
            states[(b0 + bb) * NSTATE + jj];
    }
    __syncthreads();

    // ---- Sensory reduction (once) ----
    float sden[HB], snum[HB];
    #pragma unroll
    for (int k = 0; k < HB; k++) { sden[k] = 0.0f; snum[k] = 0.0f; }

    const int smax = __reduce_max_sync(0xFFFFFFFFu, g_cscnt[t]);
    #pragma unroll 2
    for (int c = 0; c < smax; c++) {
        float4 p = g_csparams[c * NSTATE + t];
        int idx = (int)(__float_as_uint(p.x) & 0xFFu);
        float4 xv = sx4[h][idx];
        float t0 = ftanh(fmaf(p.x, xv.x, p.y));
        float t1 = ftanh(fmaf(p.x, xv.y, p.y));
        float t2 = ftanh(fmaf(p.x, xv.z, p.y));
        float t3 = ftanh(fmaf(p.x, xv.w, p.y));
        sden[0] = fmaf(p.z, t0, sden[0]);  snum[0] = fmaf(p.w, t0, snum[0]);
        sden[1] = fmaf(p.z, t1, sden[1]);  snum[1] = fmaf(p.w, t1, snum[1]);
        sden[2] = fmaf(p.z, t2, sden[2]);  snum[2] = fmaf(p.w, t2, snum[2]);
        sden[3] = fmaf(p.z, t3, sden[3]);  snum[3] = fmaf(p.w, t3, snum[3]);
    }
    {
        float2 sc = g_scol[t];
        #pragma unroll
        for (int k = 0; k < HB; k++) { sden[k] += sc.x; snum[k] += sc.y; }
    }

    const float gl   = gleak[j];
    const float gv   = gl * vleak[j];
    const float cmt  = cm[j] * (float)NUNFOLD;
    const float2 col = g_col[t];
    const int   rmax = __reduce_max_sync(0xFFFFFFFFu, g_ccnt[t]);

    // ---- Unfold loop ----
    for (int u = 0; u < NUNFOLD; u++) {
        float den[HB], num[HB];
        #pragma unroll
        for (int k = 0; k < HB; k++) {
            den[k] = sden[k] + col.x;
            num[k] = snum[k] + col.y;
        }

        #pragma unroll 2
        for (int c = 0; c < rmax; c++) {
            float4 p = g_cparams[c * NSTATE + t];
            int idx = (int)(__float_as_uint(p.x) & 0xFFu);
            float4 vv = sv4[h][idx];
            float t0 = ftanh(fmaf(p.x, vv.x, p.y));
            float t1 = ftanh(fmaf(p.x, vv.y, p.y));
            float t2 = ftanh(fmaf(p.x, vv.z, p.y));
            float t3 = ftanh(fmaf(p.x, vv.w, p.y));
            den[0] = fmaf(p.z, t0, den[0]);  num[0] = fmaf(p.w, t0, num[0]);
            den[1] = fmaf(p.z, t1, den[1]);  num[1] = fmaf(p.w, t1, num[1]);
            den[2] = fmaf(p.z, t2, den[2]);  num[2] = fmaf(p.w, t2, num[2]);
            den[3] = fmaf(p.z, t3, den[3]);  num[3] = fmaf(p.w, t3, num[3]);
        }

        __syncthreads();
        {
            float4 vold = sv4[h][j];
            float4 vnew;
            vnew.x = fmaf(cmt, vold.x, gv * num[0]) * frcp(cmt + gl + den[0] + EPSV);
            vnew.y = fmaf(cmt, vold.y, gv * num[1]) * frcp(cmt + gl + den[1] + EPSV);
            vnew.z = fmaf(cmt, vold.z, gv * num[2]) * frcp(cmt + gl + den[2] + EPSV);
            vnew.w = fmaf(cmt, vold.w, gv * num[3]) * frcp(cmt + gl + den[3] + EPSV);
            sv4[h][j] = vnew;
        }
        __syncthreads();
    }

    // ---- Write outputs: [outputs (B,M)] then [v_pre (B,N)] ----
    const float ow = (j < MOUT) ? output_w[j] : 0.0f;
    const float ob = (j < MOUT) ? output_b[j] : 0.0f;
    float4 vfin = sv4[h][j];
    float vk[HB] = {vfin.x, vfin.y, vfin.z, vfin.w};
    #pragma unroll
    for (int k = 0; k < HB; k++) {
        int b = b0 + h * HB + k;
        out[BATCH * MOUT + b * NSTATE + j] = vk[k];
        if (j < MOUT)
            out[b * MOUT + j] = fmaf(vk[k], ow, ob);
    }
}

extern "C" void kernel_launch(void* const* d_in, const int* in_sizes, int n_in,
                              void* d_out, int out_size)
{
    const float* inputs   = (const float*)d_in[0];
    const float* states   = (const float*)d_in[1];
    const float* gleak    = (const float*)d_in[2];
    const float* vleak    = (const float*)d_in[3];
    const float* cm       = (const float*)d_in[4];
    const float* sigma    = (const float*)d_in[5];
    const float* mu       = (const float*)d_in[6];
    const float* w        = (const float*)d_in[7];
    const float* erev     = (const float*)d_in[8];
    const float* ssigma   = (const float*)d_in[9];
    const float* smu      = (const float*)d_in[10];
    const float* sw       = (const float*)d_in[11];
    const float* serev    = (const float*)d_in[12];
    const float* input_w  = (const float*)d_in[13];
    const float* input_b  = (const float*)d_in[14];
    const float* output_w = (const float*)d_in[15];
    const float* output_b = (const float*)d_in[16];
    const float* mask     = (const float*)d_in[17];
    const float* smask    = (const float*)d_in[18];
    float* out = (float*)d_out;

    count_kernel<<<32, 256>>>(mask, smask);
    rank_kernel<<<1, 256>>>();
    compact_kernel<<<64, 256>>>(sigma, mu, w, erev, mask,
                                ssigma, smu, sw, serev, smask);
    reorder_kernel<<<2, 256>>>();

    ltc_kernel<<<BATCH / BB, 512>>>(
        inputs, states, gleak, vleak, cm,
        input_w, input_b, output_w, output_b, out);
}

// round 7
// speedup vs baseline: 1.7383x; 1.7383x over previous
#include <cuda_runtime.h>
#include <cstdint>

#define BATCH   1024
#define SENS    128
#define NSTATE  256
#define MOUT    32
#define NUNFOLD 6
#define BB      8          // batch rows per block
#define HB      4          // batch rows per thread (two 256-thread halves)
#define EPSV    1e-8f
#define CAP_R   176        // max active pre-neurons per column
#define CAP_S   104        // sensory cap

// Compacted params (indexed by SLOT = sorted column order), tanh form:
//   sigmoid(s*(v-m)) = 0.5 + 0.5*tanh(0.5*s*(v-m))
//   x = 0.5*sigma (low 8 mantissa bits carry pre-neuron index)
//   y = -0.5*sigma*mu,  z = 0.5*w*mask,  w = 0.5*w*erev*mask
// Entries are emitted sorted by rotated bank-group ((idx&7) - slot) & 7 so the
// shared-memory gather in the main loop is near conflict-free.
__device__ float4 g_cparams[CAP_R * NSTATE];
__device__ float4 g_csparams[CAP_S * NSTATE];
__device__ int    g_ccnt[NSTATE];
__device__ int    g_cscnt[NSTATE];
__device__ float2 g_col[NSTATE];
__device__ float2 g_scol[NSTATE];
__device__ int    g_rcntJ[NSTATE];
__device__ int    g_scntJ[NSTATE];
__device__ int    g_perm[NSTATE];     // slot -> column

__device__ __forceinline__ float ftanh(float x) {
    float y; asm("tanh.approx.f32 %0, %1;" : "=f"(y) : "f"(x)); return y;
}
__device__ __forceinline__ float frcp(float x) {
    float y; asm("rcp.approx.ftz.f32 %0, %1;" : "=f"(y) : "f"(x)); return y;
}

// ---- Pass 1: per-column active counts (one warp per column) ----
__global__ void count_kernel(const float* __restrict__ mask,
                             const float* __restrict__ smask)
{
    int warp = (blockIdx.x * blockDim.x + threadIdx.x) >> 5;
    int lane = threadIdx.x & 31;
    if (warp >= NSTATE) return;
    int j = warp;
    int rc = 0, sc = 0;
    for (int i = lane; i < NSTATE; i += 32) rc += (mask [i * NSTATE + j] != 0.0f);
    for (int s = lane; s < SENS;   s += 32) sc += (smask[s * NSTATE + j] != 0.0f);
    #pragma unroll
    for (int o = 16; o; o >>= 1) {
        rc += __shfl_xor_sync(0xFFFFFFFFu, rc, o);
        sc += __shfl_xor_sync(0xFFFFFFFFu, sc, o);
    }
    if (lane == 0) { g_rcntJ[j] = rc; g_scntJ[j] = sc; }
}

// ---- Pass 2: deterministic rank by weight, slot->column perm ----
__global__ void rank_kernel()
{
    __shared__ int key[NSTATE];
    int j = threadIdx.x;
    key[j] = NUNFOLD * g_rcntJ[j] + g_scntJ[j];
    __syncthreads();
    int kj = key[j];
    int r = 0;
    for (int k = 0; k < NSTATE; k++) {
        int kk = key[k];
        r += (kk < kj) || (kk == kj && k < j);
    }
    g_perm[r] = j;
}

// ---- Pass 3: compaction with in-line bank-group scheduling ----
// warps [0, NSTATE): recurrent; warps [NSTATE, 2*NSTATE): sensory.
// Entry handled by lane l has bank-group l&7 (chunk base multiple of 32).
// Target position = (#entries in groups earlier in rotation ((g-slot)&7))
//                 + rank within own group. Closed form, no simulation.
__global__ void compact_kernel(const float* __restrict__ sigma, const float* __restrict__ mu,
                               const float* __restrict__ w,     const float* __restrict__ erev,
                               const float* __restrict__ mask,
                               const float* __restrict__ ssigma, const float* __restrict__ smu,
                               const float* __restrict__ sw,     const float* __restrict__ serev,
                               const float* __restrict__ smask)
{
    const unsigned FULL = 0xFFFFFFFFu;
    int warp = (blockIdx.x * blockDim.x + threadIdx.x) >> 5;
    int lane = threadIdx.x & 31;
    if (warp >= 2 * NSTATE) return;

    const bool rec  = (warp < NSTATE);
    const int  slot = rec ? warp : warp - NSTATE;
    const int  j    = g_perm[slot];
    const int  NCH  = rec ? (NSTATE / 32) : (SENS / 32);   // 8 or 4
    const int  CAP  = rec ? CAP_R : CAP_S;
    float4*    buf  = rec ? g_cparams : g_csparams;

    const int      lg = lane & 7;
    const unsigned mg = 0x01010101u << lg;
    const unsigned lo = (1u << lane) - 1u;

    const float* p_sig = rec ? sigma : ssigma;
    const float* p_mu  = rec ? mu    : smu;
    const float* p_w   = rec ? w     : sw;
    const float* p_er  = rec ? erev  : serev;
    const float* p_m   = rec ? mask  : smask;

    // Pass A: ballots per chunk
    unsigned bal[8];
    #pragma unroll
    for (int ch = 0; ch < 8; ch++) {
        bal[ch] = 0u;
        if (ch < NCH) {
            int off = (ch * 32 + lane) * NSTATE + j;
            bal[ch] = __ballot_sync(FULL, p_m[off] != 0.0f);
        }
    }
    // my group's total count
    int mycnt = 0;
    #pragma unroll
    for (int ch = 0; ch < 8; ch++) mycnt += __popc(bal[ch] & mg);

    // rotation prefix + total count
    const int myord = (lg - slot) & 7;
    int pre = 0, cnt = 0;
    #pragma unroll
    for (int g = 0; g < 8; g++) {
        int cg = __shfl_sync(FULL, mycnt, g);   // lane g holds group-g count
        cnt += cg;
        if (((g - slot) & 7) < myord) pre += cg;
    }

    // Pass B: emit entries at scheduled positions
    int rbase = 0;
    float sz = 0.0f, sn = 0.0f;
    #pragma unroll
    for (int ch = 0; ch < 8; ch++) {
        if (ch >= NCH) break;
        int i   = ch * 32 + lane;
        int off = i * NSTATE + j;
        float m = p_m[off];
        if (m != 0.0f) {
            float sg = 0.5f * p_sig[off];
            float y  = -sg * p_mu[off];
            float z  = 0.5f * p_w[off] * m;
            float wn = 0.5f * p_w[off] * p_er[off] * m;
            uint32_t xb = (__float_as_uint(sg) & 0xFFFFFF00u) | (uint32_t)i;
            sz += z; sn += wn;
            int k = pre + rbase + __popc(bal[ch] & mg & lo);
            if (k < CAP)
                buf[k * NSTATE + slot] = make_float4(__uint_as_float(xb), y, z, wn);
        }
        rbase += __popc(bal[ch] & mg);
    }
    #pragma unroll
    for (int o = 16; o; o >>= 1) {
        sz += __shfl_xor_sync(FULL, sz, o);
        sn += __shfl_xor_sync(FULL, sn, o);
    }
    int ccnt = (cnt < CAP) ? cnt : CAP;
    if (lane == 0) {
        if (rec) { g_ccnt[slot]  = ccnt; g_col[slot]  = make_float2(sz, sn); }
        else     { g_cscnt[slot] = ccnt; g_scol[slot] = make_float2(sz, sn); }
    }
    // group-aligned zero padding
    for (int p = ccnt + lane; p < CAP; p += 32) {
        uint32_t xb = __float_as_uint(1.0f) | (uint32_t)((slot + p) & 7);
        buf[p * NSTATE + slot] = make_float4(__uint_as_float(xb), 0.0f, 0.0f, 0.0f);
    }
}

// ---- Main kernel ----
__global__ __launch_bounds__(512, 1)
void ltc_kernel(const float* __restrict__ inputs, const float* __restrict__ states,
                const float* __restrict__ gleak,  const float* __restrict__ vleak,
                const float* __restrict__ cm,
                const float* __restrict__ input_w, const float* __restrict__ input_b,
                const float* __restrict__ output_w, const float* __restrict__ output_b,
                float* __restrict__ out)
{
    __shared__ float4 sx4[2][SENS];      // mapped sensory inputs
    __shared__ float4 sv4[2][NSTATE];    // current state

    const int tid = threadIdx.x;
    const int t   = tid & (NSTATE - 1);  // slot
    const int h   = tid >> 8;            // batch half
    const int b0  = blockIdx.x * BB;
    const int j   = g_perm[t];           // this thread's column

    float* sxf = (float*)sx4;
    float* svf = (float*)sv4;
    for (int q = tid; q < BB * SENS; q += 512) {
        int bb = q >> 7, s = q & (SENS - 1);
        sxf[((bb >> 2) * SENS + s) * 4 + (bb & 3)] =
            inputs[(b0 + bb) * SENS + s] * input_w[s] + input_b[s];
    }
    for (int q = tid; q < BB * NSTATE; q += 512) {
        int bb = q >> 8, jj = q & (NSTATE - 1);
        svf[((bb >> 2) * NSTATE + jj) * 4 + (bb & 3)] =
            states[(b0 + bb) * NSTATE + jj];
    }
    __syncthreads();

    // ---- Sensory reduction (once) ----
    float sden[HB], snum[HB];
    #pragma unroll
    for (int k = 0; k < HB; k++) { sden[k] = 0.0f; snum[k] = 0.0f; }

    const int smax = __reduce_max_sync(0xFFFFFFFFu, g_cscnt[t]);
    #pragma unroll 2
    for (int c = 0; c < smax; c++) {
        float4 p = g_csparams[c * NSTATE + t];
        int idx = (int)(__float_as_uint(p.x) & 0xFFu);
        float4 xv = sx4[h][idx];
        float t0 = ftanh(fmaf(p.x, xv.x, p.y));
        float t1 = ftanh(fmaf(p.x, xv.y, p.y));
        float t2 = ftanh(fmaf(p.x, xv.z, p.y));
        float t3 = ftanh(fmaf(p.x, xv.w, p.y));
        sden[0] = fmaf(p.z, t0, sden[0]);  snum[0] = fmaf(p.w, t0, snum[0]);
        sden[1] = fmaf(p.z, t1, sden[1]);  snum[1] = fmaf(p.w, t1, snum[1]);
        sden[2] = fmaf(p.z, t2, sden[2]);  snum[2] = fmaf(p.w, t2, snum[2]);
        sden[3] = fmaf(p.z, t3, sden[3]);  snum[3] = fmaf(p.w, t3, snum[3]);
    }
    {
        float2 sc = g_scol[t];
        #pragma unroll
        for (int k = 0; k < HB; k++) { sden[k] += sc.x; snum[k] += sc.y; }
    }

    const float gl   = gleak[j];
    const float gv   = gl * vleak[j];
    const float cmt  = cm[j] * (float)NUNFOLD;
    const float2 col = g_col[t];
    const int   rmax = __reduce_max_sync(0xFFFFFFFFu, g_ccnt[t]);

    // ---- Unfold loop ----
    for (int u = 0; u < NUNFOLD; u++) {
        float den[HB], num[HB];
        #pragma unroll
        for (int k = 0; k < HB; k++) {
            den[k] = sden[k] + col.x;
            num[k] = snum[k] + col.y;
        }

        #pragma unroll 2
        for (int c = 0; c < rmax; c++) {
            float4 p = g_cparams[c * NSTATE + t];
            int idx = (int)(__float_as_uint(p.x) & 0xFFu);
            float4 vv = sv4[h][idx];
            float t0 = ftanh(fmaf(p.x, vv.x, p.y));
            float t1 = ftanh(fmaf(p.x, vv.y, p.y));
            float t2 = ftanh(fmaf(p.x, vv.z, p.y));
            float t3 = ftanh(fmaf(p.x, vv.w, p.y));
            den[0] = fmaf(p.z, t0, den[0]);  num[0] = fmaf(p.w, t0, num[0]);
            den[1] = fmaf(p.z, t1, den[1]);  num[1] = fmaf(p.w, t1, num[1]);
            den[2] = fmaf(p.z, t2, den[2]);  num[2] = fmaf(p.w, t2, num[2]);
            den[3] = fmaf(p.z, t3, den[3]);  num[3] = fmaf(p.w, t3, num[3]);
        }

        __syncthreads();
        {
            float4 vold = sv4[h][j];
            float4 vnew;
            vnew.x = fmaf(cmt, vold.x, gv * num[0]) * frcp(cmt + gl + den[0] + EPSV);
            vnew.y = fmaf(cmt, vold.y, gv * num[1]) * frcp(cmt + gl + den[1] + EPSV);
            vnew.z = fmaf(cmt, vold.z, gv * num[2]) * frcp(cmt + gl + den[2] + EPSV);
            vnew.w = fmaf(cmt, vold.w, gv * num[3]) * frcp(cmt + gl + den[3] + EPSV);
            sv4[h][j] = vnew;
        }
        __syncthreads();
    }

    // ---- Write outputs: [outputs (B,M)] then [v_pre (B,N)] ----
    const float ow = (j < MOUT) ? output_w[j] : 0.0f;
    const float ob = (j < MOUT) ? output_b[j] : 0.0f;
    float4 vfin = sv4[h][j];
    float vk[HB] = {vfin.x, vfin.y, vfin.z, vfin.w};
    #pragma unroll
    for (int k = 0; k < HB; k++) {
        int b = b0 + h * HB + k;
        out[BATCH * MOUT + b * NSTATE + j] = vk[k];
        if (j < MOUT)
            out[b * MOUT + j] = fmaf(vk[k], ow, ob);
    }
}

extern "C" void kernel_launch(void* const* d_in, const int* in_sizes, int n_in,
                              void* d_out, int out_size)
{
    const float* inputs   = (const float*)d_in[0];
    const float* states   = (const float*)d_in[1];
    const float* gleak    = (const float*)d_in[2];
    const float* vleak    = (const float*)d_in[3];
    const float* cm       = (const float*)d_in[4];
    const float* sigma    = (const float*)d_in[5];
    const float* mu       = (const float*)d_in[6];
    const float* w        = (const float*)d_in[7];
    const float* erev     = (const float*)d_in[8];
    const float* ssigma   = (const float*)d_in[9];
    const float* smu      = (const float*)d_in[10];
    const float* sw       = (const float*)d_in[11];
    const float* serev    = (const float*)d_in[12];
    const float* input_w  = (const float*)d_in[13];
    const float* input_b  = (const float*)d_in[14];
    const float* output_w = (const float*)d_in[15];
    const float* output_b = (const float*)d_in[16];
    const float* mask     = (const float*)d_in[17];
    const float* smask    = (const float*)d_in[18];
    float* out = (float*)d_out;

    count_kernel<<<32, 256>>>(mask, smask);
    rank_kernel<<<1, 256>>>();
    compact_kernel<<<64, 256>>>(sigma, mu, w, erev, mask,
                                ssigma, smu, sw, serev, smask);

    ltc_kernel<<<BATCH / BB, 512>>>(
        inputs, states, gleak, vleak, cm,
        input_w, input_b, output_w, output_b, out);
}